// round 2
// baseline (speedup 1.0000x reference)
#include <cuda_runtime.h>
#include <cstdint>

// ReverseDiffusion: out = where(x_t == 50256, categorical(key42, topk_topp(logits)), x_t)
// Input x_t is an integer buffer (int32 or int64, runtime-detected);
// OUTPUT IS WRITTEN AS FLOAT32 (harness canonicalizes int64 -> float32).

#define TOPK 50
#define TOPP 0.9f
#define MASK_ID 50256LL

__device__ int g_mode;   // 0 = int32, 1 = int64, 2 = float32

// ---------------- dtype detection ----------------
// Reads exactly n_words 32-bit words (== element count), in-bounds for all dtypes.
//  - float32 tokens >= 1.0 have bits >= 0x3F800000 (large)      -> mode 2
//  - int64: odd words are high halves of small tokens, all zero -> mode 1
//  - int32: odd words are random tokens, not all zero           -> mode 0
__global__ void detect_dtype_kernel(const unsigned* __restrict__ w, int n_words) {
    __shared__ int s_oddnz, s_large;
    if (threadIdx.x == 0) { s_oddnz = 0; s_large = 0; }
    __syncthreads();
    int oddnz = 0, large = 0;
    for (int i = threadIdx.x; i < n_words; i += blockDim.x) {
        unsigned v = w[i];
        if (v >= 0x01000000u) large++;
        if ((i & 1) && v != 0u) oddnz++;
    }
    if (oddnz) atomicAdd(&s_oddnz, oddnz);
    if (large) atomicAdd(&s_large, large);
    __syncthreads();
    if (threadIdx.x == 0) {
        if (s_large > 0)       g_mode = 2;
        else if (s_oddnz == 0) g_mode = 1;
        else                   g_mode = 0;
    }
}

// ---------------- helpers ----------------
__device__ __forceinline__ unsigned f2key(float f) {
    unsigned u = __float_as_uint(f);
    return (u & 0x80000000u) ? ~u : (u | 0x80000000u);
}
__device__ __forceinline__ unsigned rotl32(unsigned x, int n) {
    return (x << n) | (x >> (32 - n));
}

// JAX threefry2x32, key = (0, 42)
__device__ void threefry_0_42(unsigned x0, unsigned x1, unsigned& o0, unsigned& o1) {
    const unsigned k0 = 0u, k1 = 42u;
    const unsigned k2 = k0 ^ k1 ^ 0x1BD11BDAu;
    unsigned v0 = x0 + k0, v1 = x1 + k1;
#define TF_ROUND(r) { v0 += v1; v1 = rotl32(v1, r); v1 ^= v0; }
    TF_ROUND(13) TF_ROUND(15) TF_ROUND(26) TF_ROUND(6)
    v0 += k1; v1 += k2 + 1u;
    TF_ROUND(17) TF_ROUND(29) TF_ROUND(16) TF_ROUND(24)
    v0 += k2; v1 += k0 + 2u;
    TF_ROUND(13) TF_ROUND(15) TF_ROUND(26) TF_ROUND(6)
    v0 += k0; v1 += k1 + 3u;
    TF_ROUND(17) TF_ROUND(29) TF_ROUND(16) TF_ROUND(24)
    v0 += k1; v1 += k2 + 4u;
    TF_ROUND(13) TF_ROUND(15) TF_ROUND(26) TF_ROUND(6)
    v0 += k2; v1 += k0 + 5u;
#undef TF_ROUND
    o0 = v0; o1 = v1;
}

// gumbel noise at flat index i of the (B,S,VOCAB) array, exactly as
// jax.random.gumbel(key(42), shape): iota split into halves through threefry.
__device__ float gumbel_at(unsigned long long i, unsigned long long half) {
    unsigned x0, x1, o0, o1;
    if (i < half) { x0 = (unsigned)i;          x1 = (unsigned)(i + half); }
    else          { x0 = (unsigned)(i - half); x1 = (unsigned)i;          }
    threefry_0_42(x0, x1, o0, o1);
    unsigned bits = (i < half) ? o0 : o1;
    float u = __uint_as_float((bits >> 9) | 0x3f800000u) - 1.0f;
    u = fmaxf(u, 1.17549435e-38f);
    return -logf(-logf(u));
}

// ---------------- main kernel: one block per (b,s) position ----------------
__global__ void __launch_bounds__(256)
rd_kernel(const float* __restrict__ logits, const void* __restrict__ xt,
          float* __restrict__ out, int vocab, unsigned long long total) {
    const int r = blockIdx.x;
    const int tid = threadIdx.x;
    const int mode = g_mode;

    long long xv;
    if (mode == 1)      xv = ((const long long*)xt)[r];
    else if (mode == 0) xv = (long long)((const int*)xt)[r];
    else                xv = __float2ll_rn(((const float*)xt)[r]);

    if (xv != MASK_ID) {                     // fast path: copy through as float
        if (tid == 0) out[r] = (float)xv;
        return;
    }

    // ---------- heavy path: exact top-k -> top-p -> gumbel argmax ----------
    const float* row = logits + (size_t)r * (size_t)vocab;
    __shared__ int s_cnt;

    // 1) 50th-largest key via MSB-first binary search
    unsigned T = 0;
    for (int bit = 31; bit >= 0; --bit) {
        unsigned cand = T | (1u << bit);
        if (tid == 0) s_cnt = 0;
        __syncthreads();
        int c = 0;
        for (int v = tid; v < vocab; v += blockDim.x)
            c += (f2key(row[v]) >= cand);
        if (c) atomicAdd(&s_cnt, c);
        __syncthreads();
        int cnt = s_cnt;
        __syncthreads();
        if (cnt >= TOPK) T = cand;
    }

    // 2) count strictly greater
    if (tid == 0) s_cnt = 0;
    __syncthreads();
    {
        int c = 0;
        for (int v = tid; v < vocab; v += blockDim.x)
            c += (f2key(row[v]) > T);
        if (c) atomicAdd(&s_cnt, c);
    }
    __syncthreads();
    const int n_greater = s_cnt;            // <= 49
    const int need_eq = TOPK - n_greater;   // >= 1
    __syncthreads();

    // 3) gather the top-k set (stable tie-break by lowest index)
    __shared__ float sval[TOPK];
    __shared__ int   sidx[TOPK];
    __shared__ int   s_ng, s_neq;
    __shared__ int   eq_idx[128];
    if (tid == 0) { s_ng = 0; s_neq = 0; }
    __syncthreads();
    for (int v = tid; v < vocab; v += blockDim.x) {
        unsigned k = f2key(row[v]);
        if (k > T) {
            int p = atomicAdd(&s_ng, 1);
            sval[p] = row[v]; sidx[p] = v;
        } else if (k == T) {
            int p = atomicAdd(&s_neq, 1);
            if (p < 128) eq_idx[p] = v;
        }
    }
    __syncthreads();

    if (tid == 0) {
        int ne = s_neq; if (ne > 128) ne = 128;
        for (int a = 0; a < need_eq; ++a) {
            int mb = a;
            for (int b2 = a + 1; b2 < ne; ++b2)
                if (eq_idx[b2] < eq_idx[mb]) mb = b2;
            int t = eq_idx[a]; eq_idx[a] = eq_idx[mb]; eq_idx[mb] = t;
            sval[n_greater + a] = row[eq_idx[a]];
            sidx[n_greater + a] = eq_idx[a];
        }
        // sort 50: descending value, tie -> ascending index
        for (int a = 1; a < TOPK; ++a) {
            float v = sval[a]; int ix = sidx[a];
            int b2 = a - 1;
            while (b2 >= 0 && (sval[b2] < v || (sval[b2] == v && sidx[b2] > ix))) {
                sval[b2 + 1] = sval[b2]; sidx[b2 + 1] = sidx[b2]; --b2;
            }
            sval[b2 + 1] = v; sidx[b2 + 1] = ix;
        }
        // softmax + right-shifted cumsum nucleus cutoff (prefix of length m)
        float vmax = sval[0];
        float e[TOPK];
        float denom = 0.f;
        for (int j = 0; j < TOPK; ++j) { e[j] = expf(sval[j] - vmax); denom += e[j]; }
        float cumprev = 0.f;
        int m = 0;
        for (int j = 0; j < TOPK; ++j) {
            if (j != 0 && !(cumprev <= TOPP)) break;
            ++m;
            cumprev += e[j] / denom;
        }
        // gumbel-argmax over survivors; tie -> smallest vocab index
        unsigned long long half = total >> 1;
        float best = -1e30f; int besti = 0x7fffffff;
        for (int j = 0; j < m; ++j) {
            unsigned long long i =
                (unsigned long long)r * (unsigned long long)vocab + (unsigned long long)sidx[j];
            float score = sval[j] + gumbel_at(i, half);
            if (score > best || (score == best && sidx[j] < besti)) {
                best = score; besti = sidx[j];
            }
        }
        out[r] = (float)besti;
    }
}

extern "C" void kernel_launch(void* const* d_in, const int* in_sizes, int n_in,
                              void* d_out, int out_size) {
    int li = 0, xi = 1;
    if (n_in >= 2 && in_sizes[1] > in_sizes[0]) { li = 1; xi = 0; }  // logits = bigger input
    const float* logits = (const float*)d_in[li];
    const void*  xt     = d_in[xi];
    const int npos  = out_size;                     // B*S = 2048 (output element count)
    const int vocab = in_sizes[li] / npos;          // 50257
    const unsigned long long total = (unsigned long long)in_sizes[li];

    detect_dtype_kernel<<<1, 256>>>((const unsigned*)xt, in_sizes[xi] < npos ? in_sizes[xi] : npos);
    rd_kernel<<<npos, 256>>>(logits, xt, (float*)d_out, vocab, total);
}

// round 3
// speedup vs baseline: 1.5907x; 1.5907x over previous
#include <cuda_runtime.h>
#include <cstdint>

// ReverseDiffusion: out = where(x_t == 50256, categorical(key42, topk_topp(logits)), x_t)
// Single-launch version: dtype detection + copy + (rare) exact sampling in one kernel.
// Input x_t dtype runtime-detected (int32 / int64 / float32); output is float32.

#define TOPK 50
#define TOPP 0.9f
#define MASK_ID 50256LL
#define BLK 128

// ---------------- helpers ----------------
__device__ __forceinline__ unsigned f2key(float f) {
    unsigned u = __float_as_uint(f);
    return (u & 0x80000000u) ? ~u : (u | 0x80000000u);
}
__device__ __forceinline__ unsigned rotl32(unsigned x, int n) {
    return (x << n) | (x >> (32 - n));
}

// JAX threefry2x32, key = (0, 42)
__device__ void threefry_0_42(unsigned x0, unsigned x1, unsigned& o0, unsigned& o1) {
    const unsigned k0 = 0u, k1 = 42u;
    const unsigned k2 = k0 ^ k1 ^ 0x1BD11BDAu;
    unsigned v0 = x0 + k0, v1 = x1 + k1;
#define TF_ROUND(r) { v0 += v1; v1 = rotl32(v1, r); v1 ^= v0; }
    TF_ROUND(13) TF_ROUND(15) TF_ROUND(26) TF_ROUND(6)
    v0 += k1; v1 += k2 + 1u;
    TF_ROUND(17) TF_ROUND(29) TF_ROUND(16) TF_ROUND(24)
    v0 += k2; v1 += k0 + 2u;
    TF_ROUND(13) TF_ROUND(15) TF_ROUND(26) TF_ROUND(6)
    v0 += k0; v1 += k1 + 3u;
    TF_ROUND(17) TF_ROUND(29) TF_ROUND(16) TF_ROUND(24)
    v0 += k1; v1 += k2 + 4u;
    TF_ROUND(13) TF_ROUND(15) TF_ROUND(26) TF_ROUND(6)
    v0 += k2; v1 += k0 + 5u;
#undef TF_ROUND
    o0 = v0; o1 = v1;
}

// gumbel noise at flat index i of the (B,S,VOCAB) array, exactly as
// jax.random.gumbel(key(42), shape): iota split into halves through threefry.
__device__ float gumbel_at(unsigned long long i, unsigned long long half) {
    unsigned x0, x1, o0, o1;
    if (i < half) { x0 = (unsigned)i;          x1 = (unsigned)(i + half); }
    else          { x0 = (unsigned)(i - half); x1 = (unsigned)i;          }
    threefry_0_42(x0, x1, o0, o1);
    unsigned bits = (i < half) ? o0 : o1;
    float u = __uint_as_float((bits >> 9) | 0x3f800000u) - 1.0f;
    u = fmaxf(u, 1.17549435e-38f);
    return -logf(-logf(u));
}

// ---------------- single fused kernel ----------------
// Grid: ceil(npos/BLK) CTAs, one THREAD per position. Masked positions are
// collected per-block and then handled block-cooperatively (exact JAX math).
__global__ void __launch_bounds__(BLK)
rd_fused(const float* __restrict__ logits, const void* __restrict__ xt,
         float* __restrict__ out, int vocab, int npos, unsigned long long total) {
    const int tid = threadIdx.x;

    // ---- 1) dtype detection (block-local; every block derives the same answer
    //         from the same npos 32-bit words — in-bounds for all candidate dtypes)
    //  float32 tokens >= 1.0 have bits >= 0x3F800000 (large)      -> mode 2
    //  int64: odd words are high halves of small tokens, all zero -> mode 1
    //  int32: odd words are random tokens, not all zero           -> mode 0
    __shared__ int s_oddnz, s_large;
    if (tid == 0) { s_oddnz = 0; s_large = 0; }
    __syncthreads();
    {
        const unsigned* w = (const unsigned*)xt;
        int oddnz = 0, large = 0;
        for (int i = tid; i < npos; i += BLK) {
            unsigned v = w[i];
            if (v >= 0x01000000u) large++;
            if ((i & 1) && v != 0u) oddnz++;
        }
        if (oddnz) atomicAdd(&s_oddnz, oddnz);
        if (large) atomicAdd(&s_large, large);
    }
    __syncthreads();
    const int mode = (s_large > 0) ? 2 : ((s_oddnz == 0) ? 1 : 0);

    // ---- 2) fast path: one thread per position, collect masked ones
    __shared__ int s_masked[BLK];
    __shared__ int s_nmask;
    if (tid == 0) s_nmask = 0;
    __syncthreads();
    {
        int r = blockIdx.x * BLK + tid;
        if (r < npos) {
            long long xv;
            if (mode == 1)      xv = ((const long long*)xt)[r];
            else if (mode == 0) xv = (long long)((const int*)xt)[r];
            else                xv = __float2ll_rn(((const float*)xt)[r]);
            if (xv != MASK_ID) out[r] = (float)xv;
            else { int p = atomicAdd(&s_nmask, 1); s_masked[p] = r; }
        }
    }
    __syncthreads();
    const int nmask = s_nmask;
    if (nmask == 0) return;

    // ---- 3) heavy path (rare): exact top-k -> top-p -> gumbel argmax,
    //         block-cooperative, one masked row at a time.
    __shared__ int   s_cnt;
    __shared__ float sval[TOPK];
    __shared__ int   sidx[TOPK];
    __shared__ int   s_ng, s_neq;
    __shared__ int   eq_idx[128];

    for (int mi = 0; mi < nmask; ++mi) {
        const int r = s_masked[mi];
        const float* row = logits + (size_t)r * (size_t)vocab;

        // 3a) 50th-largest key via MSB-first binary search
        unsigned T = 0;
        for (int bit = 31; bit >= 0; --bit) {
            unsigned cand = T | (1u << bit);
            if (tid == 0) s_cnt = 0;
            __syncthreads();
            int c = 0;
            for (int v = tid; v < vocab; v += BLK)
                c += (f2key(row[v]) >= cand);
            if (c) atomicAdd(&s_cnt, c);
            __syncthreads();
            int cnt = s_cnt;
            __syncthreads();
            if (cnt >= TOPK) T = cand;
        }

        // 3b) count strictly greater
        if (tid == 0) s_cnt = 0;
        __syncthreads();
        {
            int c = 0;
            for (int v = tid; v < vocab; v += BLK)
                c += (f2key(row[v]) > T);
            if (c) atomicAdd(&s_cnt, c);
        }
        __syncthreads();
        const int n_greater = s_cnt;            // <= 49
        const int need_eq = TOPK - n_greater;   // >= 1
        __syncthreads();

        // 3c) gather the top-k set (stable tie-break by lowest index)
        if (tid == 0) { s_ng = 0; s_neq = 0; }
        __syncthreads();
        for (int v = tid; v < vocab; v += BLK) {
            unsigned k = f2key(row[v]);
            if (k > T) {
                int p = atomicAdd(&s_ng, 1);
                sval[p] = row[v]; sidx[p] = v;
            } else if (k == T) {
                int p = atomicAdd(&s_neq, 1);
                if (p < 128) eq_idx[p] = v;
            }
        }
        __syncthreads();

        if (tid == 0) {
            int ne = s_neq; if (ne > 128) ne = 128;
            // pick the need_eq smallest indices among threshold-equal tokens
            for (int a = 0; a < need_eq; ++a) {
                int mb = a;
                for (int b2 = a + 1; b2 < ne; ++b2)
                    if (eq_idx[b2] < eq_idx[mb]) mb = b2;
                int t = eq_idx[a]; eq_idx[a] = eq_idx[mb]; eq_idx[mb] = t;
                sval[n_greater + a] = row[eq_idx[a]];
                sidx[n_greater + a] = eq_idx[a];
            }
            // sort 50: descending value, tie -> ascending index
            for (int a = 1; a < TOPK; ++a) {
                float v = sval[a]; int ix = sidx[a];
                int b2 = a - 1;
                while (b2 >= 0 && (sval[b2] < v || (sval[b2] == v && sidx[b2] > ix))) {
                    sval[b2 + 1] = sval[b2]; sidx[b2 + 1] = sidx[b2]; --b2;
                }
                sval[b2 + 1] = v; sidx[b2 + 1] = ix;
            }
            // softmax + right-shifted cumsum nucleus cutoff (prefix of length m)
            float vmax = sval[0];
            float e[TOPK];
            float denom = 0.f;
            for (int j = 0; j < TOPK; ++j) { e[j] = expf(sval[j] - vmax); denom += e[j]; }
            float cumprev = 0.f;
            int m = 0;
            for (int j = 0; j < TOPK; ++j) {
                if (j != 0 && !(cumprev <= TOPP)) break;
                ++m;
                cumprev += e[j] / denom;
            }
            // gumbel-argmax over survivors; tie -> smallest vocab index
            unsigned long long half = total >> 1;
            float best = -1e30f; int besti = 0x7fffffff;
            for (int j = 0; j < m; ++j) {
                unsigned long long i =
                    (unsigned long long)r * (unsigned long long)vocab + (unsigned long long)sidx[j];
                float score = sval[j] + gumbel_at(i, half);
                if (score > best || (score == best && sidx[j] < besti)) {
                    best = score; besti = sidx[j];
                }
            }
            out[r] = (float)besti;
        }
        __syncthreads();
    }
}

extern "C" void kernel_launch(void* const* d_in, const int* in_sizes, int n_in,
                              void* d_out, int out_size) {
    int li = 0, xi = 1;
    if (n_in >= 2 && in_sizes[1] > in_sizes[0]) { li = 1; xi = 0; }  // logits = bigger input
    const float* logits = (const float*)d_in[li];
    const void*  xt     = d_in[xi];
    const int npos  = out_size;                     // B*S = 2048 (output element count)
    const int vocab = in_sizes[li] / npos;          // 50257
    const unsigned long long total = (unsigned long long)in_sizes[li];

    rd_fused<<<(npos + BLK - 1) / BLK, BLK>>>(logits, xt, (float*)d_out, vocab, npos, total);
}

// round 4
// speedup vs baseline: 1.7629x; 1.1082x over previous
#include <cuda_runtime.h>
#include <cstdint>

// ReverseDiffusion: out = where(x_t == 50256, categorical(key42, topk_topp(logits)), x_t)
// Single launch; dtype detection uses a 128-word sample; the (likely) int32
// interpretation of x_t is loaded speculatively in parallel with detection.

#define TOPK 50
#define TOPP 0.9f
#define MASK_ID 50256LL
#define BLK 128

// ---------------- helpers ----------------
__device__ __forceinline__ unsigned f2key(float f) {
    unsigned u = __float_as_uint(f);
    return (u & 0x80000000u) ? ~u : (u | 0x80000000u);
}
__device__ __forceinline__ unsigned rotl32(unsigned x, int n) {
    return (x << n) | (x >> (32 - n));
}

// JAX threefry2x32, key = (0, 42)
__device__ void threefry_0_42(unsigned x0, unsigned x1, unsigned& o0, unsigned& o1) {
    const unsigned k0 = 0u, k1 = 42u;
    const unsigned k2 = k0 ^ k1 ^ 0x1BD11BDAu;
    unsigned v0 = x0 + k0, v1 = x1 + k1;
#define TF_ROUND(r) { v0 += v1; v1 = rotl32(v1, r); v1 ^= v0; }
    TF_ROUND(13) TF_ROUND(15) TF_ROUND(26) TF_ROUND(6)
    v0 += k1; v1 += k2 + 1u;
    TF_ROUND(17) TF_ROUND(29) TF_ROUND(16) TF_ROUND(24)
    v0 += k2; v1 += k0 + 2u;
    TF_ROUND(13) TF_ROUND(15) TF_ROUND(26) TF_ROUND(6)
    v0 += k0; v1 += k1 + 3u;
    TF_ROUND(17) TF_ROUND(29) TF_ROUND(16) TF_ROUND(24)
    v0 += k1; v1 += k2 + 4u;
    TF_ROUND(13) TF_ROUND(15) TF_ROUND(26) TF_ROUND(6)
    v0 += k2; v1 += k0 + 5u;
#undef TF_ROUND
    o0 = v0; o1 = v1;
}

// gumbel noise at flat index i, exactly as jax.random.gumbel(key(42), shape)
__device__ float gumbel_at(unsigned long long i, unsigned long long half) {
    unsigned x0, x1, o0, o1;
    if (i < half) { x0 = (unsigned)i;          x1 = (unsigned)(i + half); }
    else          { x0 = (unsigned)(i - half); x1 = (unsigned)i;          }
    threefry_0_42(x0, x1, o0, o1);
    unsigned bits = (i < half) ? o0 : o1;
    float u = __uint_as_float((bits >> 9) | 0x3f800000u) - 1.0f;
    u = fmaxf(u, 1.17549435e-38f);
    return -logf(-logf(u));
}

// ---------------- single fused kernel ----------------
__global__ void __launch_bounds__(BLK)
rd_fused(const float* __restrict__ logits, const void* __restrict__ xt,
         float* __restrict__ out, int vocab, int npos, unsigned long long total) {
    const int tid = threadIdx.x;
    const int r = blockIdx.x * BLK + tid;

    // ---- 1) dtype detection from a 128-word sample (words 1,3,...,255; in-bounds
    //         for every candidate dtype since npos >= 256 words in all of them).
    //  float32: sampled words are tokens >= 1.0 -> bits >= 0x3F800000 (large)
    //  int64:   sampled (odd) words are hi halves of small tokens -> all zero
    //  int32:   sampled words are random tokens -> not all zero, none large
    __shared__ int s_oddnz, s_large;
    if (tid == 0) { s_oddnz = 0; s_large = 0; }
    __syncthreads();

    const unsigned* w = (const unsigned*)xt;
    // issue BOTH loads back-to-back so their latencies overlap:
    unsigned det = w[2 * tid + 1];                     // detection sample
    int spec32 = (r < npos) ? ((const int*)xt)[r] : 0; // speculative int32 read

    if (det >= 0x01000000u) atomicAdd(&s_large, 1);
    if (det != 0u)          atomicAdd(&s_oddnz, 1);
    __syncthreads();
    const int mode = (s_large > 0) ? 2 : ((s_oddnz == 0) ? 1 : 0);

    // ---- 2) fast path: one thread per position, collect masked ones
    __shared__ int s_masked[BLK];
    __shared__ int s_nmask;
    if (tid == 0) s_nmask = 0;
    __syncthreads();
    if (r < npos) {
        long long xv;
        if (mode == 0)      xv = (long long)spec32;                    // common case: no extra load
        else if (mode == 1) xv = ((const long long*)xt)[r];
        else                xv = __float2ll_rn(((const float*)xt)[r]);
        if (xv != MASK_ID) out[r] = (float)xv;
        else { int p = atomicAdd(&s_nmask, 1); s_masked[p] = r; }
    }
    __syncthreads();
    const int nmask = s_nmask;
    if (nmask == 0) return;

    // ---- 3) heavy path (rare): exact top-k -> top-p -> gumbel argmax
    __shared__ int   s_cnt;
    __shared__ float sval[TOPK];
    __shared__ int   sidx[TOPK];
    __shared__ int   s_ng, s_neq;
    __shared__ int   eq_idx[128];

    for (int mi = 0; mi < nmask; ++mi) {
        const int row_r = s_masked[mi];
        const float* row = logits + (size_t)row_r * (size_t)vocab;

        // 3a) 50th-largest key via MSB-first binary search
        unsigned T = 0;
        for (int bit = 31; bit >= 0; --bit) {
            unsigned cand = T | (1u << bit);
            if (tid == 0) s_cnt = 0;
            __syncthreads();
            int c = 0;
            for (int v = tid; v < vocab; v += BLK)
                c += (f2key(row[v]) >= cand);
            if (c) atomicAdd(&s_cnt, c);
            __syncthreads();
            int cnt = s_cnt;
            __syncthreads();
            if (cnt >= TOPK) T = cand;
        }

        // 3b) count strictly greater
        if (tid == 0) s_cnt = 0;
        __syncthreads();
        {
            int c = 0;
            for (int v = tid; v < vocab; v += BLK)
                c += (f2key(row[v]) > T);
            if (c) atomicAdd(&s_cnt, c);
        }
        __syncthreads();
        const int n_greater = s_cnt;            // <= 49
        const int need_eq = TOPK - n_greater;   // >= 1
        __syncthreads();

        // 3c) gather the top-k set (stable tie-break by lowest index)
        if (tid == 0) { s_ng = 0; s_neq = 0; }
        __syncthreads();
        for (int v = tid; v < vocab; v += BLK) {
            unsigned k = f2key(row[v]);
            if (k > T) {
                int p = atomicAdd(&s_ng, 1);
                sval[p] = row[v]; sidx[p] = v;
            } else if (k == T) {
                int p = atomicAdd(&s_neq, 1);
                if (p < 128) eq_idx[p] = v;
            }
        }
        __syncthreads();

        if (tid == 0) {
            int ne = s_neq; if (ne > 128) ne = 128;
            for (int a = 0; a < need_eq; ++a) {
                int mb = a;
                for (int b2 = a + 1; b2 < ne; ++b2)
                    if (eq_idx[b2] < eq_idx[mb]) mb = b2;
                int t = eq_idx[a]; eq_idx[a] = eq_idx[mb]; eq_idx[mb] = t;
                sval[n_greater + a] = row[eq_idx[a]];
                sidx[n_greater + a] = eq_idx[a];
            }
            // sort 50: descending value, tie -> ascending index
            for (int a = 1; a < TOPK; ++a) {
                float v = sval[a]; int ix = sidx[a];
                int b2 = a - 1;
                while (b2 >= 0 && (sval[b2] < v || (sval[b2] == v && sidx[b2] > ix))) {
                    sval[b2 + 1] = sval[b2]; sidx[b2 + 1] = sidx[b2]; --b2;
                }
                sval[b2 + 1] = v; sidx[b2 + 1] = ix;
            }
            // softmax + right-shifted cumsum nucleus cutoff (prefix of length m)
            float vmax = sval[0];
            float e[TOPK];
            float denom = 0.f;
            for (int j = 0; j < TOPK; ++j) { e[j] = expf(sval[j] - vmax); denom += e[j]; }
            float cumprev = 0.f;
            int m = 0;
            for (int j = 0; j < TOPK; ++j) {
                if (j != 0 && !(cumprev <= TOPP)) break;
                ++m;
                cumprev += e[j] / denom;
            }
            // gumbel-argmax over survivors; tie -> smallest vocab index
            unsigned long long half = total >> 1;
            float best = -1e30f; int besti = 0x7fffffff;
            for (int j = 0; j < m; ++j) {
                unsigned long long i =
                    (unsigned long long)row_r * (unsigned long long)vocab
                    + (unsigned long long)sidx[j];
                float score = sval[j] + gumbel_at(i, half);
                if (score > best || (score == best && sidx[j] < besti)) {
                    best = score; besti = sidx[j];
                }
            }
            out[row_r] = (float)besti;
        }
        __syncthreads();
    }
}

extern "C" void kernel_launch(void* const* d_in, const int* in_sizes, int n_in,
                              void* d_out, int out_size) {
    int li = 0, xi = 1;
    if (n_in >= 2 && in_sizes[1] > in_sizes[0]) { li = 1; xi = 0; }  // logits = bigger input
    const float* logits = (const float*)d_in[li];
    const void*  xt     = d_in[xi];
    const int npos  = out_size;                     // B*S = 2048
    const int vocab = in_sizes[li] / npos;          // 50257
    const unsigned long long total = (unsigned long long)in_sizes[li];

    rd_fused<<<(npos + BLK - 1) / BLK, BLK>>>(logits, xt, (float*)d_out, vocab, npos, total);
}

// round 5
// speedup vs baseline: 1.9543x; 1.1086x over previous
#include <cuda_runtime.h>
#include <cstdint>

// ReverseDiffusion: out = where(x_t == 50256, categorical(key42, topk_topp(logits)), x_t)
// One launch, 4 positions/thread via uint4; the data load doubles as the dtype
// detection sample (per-warp ballot consensus). Exact JAX math on the rare
// masked positions.

#define TOPK 50
#define TOPP 0.9f
#define MASK_ID 50256LL
#define BLK 128

// ---------------- helpers ----------------
__device__ __forceinline__ unsigned f2key(float f) {
    unsigned u = __float_as_uint(f);
    return (u & 0x80000000u) ? ~u : (u | 0x80000000u);
}
__device__ __forceinline__ unsigned rotl32(unsigned x, int n) {
    return (x << n) | (x >> (32 - n));
}

// JAX threefry2x32, key = (0, 42)
__device__ void threefry_0_42(unsigned x0, unsigned x1, unsigned& o0, unsigned& o1) {
    const unsigned k0 = 0u, k1 = 42u;
    const unsigned k2 = k0 ^ k1 ^ 0x1BD11BDAu;
    unsigned v0 = x0 + k0, v1 = x1 + k1;
#define TF_ROUND(r) { v0 += v1; v1 = rotl32(v1, r); v1 ^= v0; }
    TF_ROUND(13) TF_ROUND(15) TF_ROUND(26) TF_ROUND(6)
    v0 += k1; v1 += k2 + 1u;
    TF_ROUND(17) TF_ROUND(29) TF_ROUND(16) TF_ROUND(24)
    v0 += k2; v1 += k0 + 2u;
    TF_ROUND(13) TF_ROUND(15) TF_ROUND(26) TF_ROUND(6)
    v0 += k0; v1 += k1 + 3u;
    TF_ROUND(17) TF_ROUND(29) TF_ROUND(16) TF_ROUND(24)
    v0 += k1; v1 += k2 + 4u;
    TF_ROUND(13) TF_ROUND(15) TF_ROUND(26) TF_ROUND(6)
    v0 += k2; v1 += k0 + 5u;
#undef TF_ROUND
    o0 = v0; o1 = v1;
}

// gumbel noise at flat index i, exactly as jax.random.gumbel(key(42), shape)
__device__ float gumbel_at(unsigned long long i, unsigned long long half) {
    unsigned x0, x1, o0, o1;
    if (i < half) { x0 = (unsigned)i;          x1 = (unsigned)(i + half); }
    else          { x0 = (unsigned)(i - half); x1 = (unsigned)i;          }
    threefry_0_42(x0, x1, o0, o1);
    unsigned bits = (i < half) ? o0 : o1;
    float u = __uint_as_float((bits >> 9) | 0x3f800000u) - 1.0f;
    u = fmaxf(u, 1.17549435e-38f);
    return -logf(-logf(u));
}

// ---------------- single fused kernel ----------------
// Each thread owns 4 consecutive positions. grid = ceil(npos/4/BLK).
__global__ void __launch_bounds__(BLK)
rd_fused(const float* __restrict__ logits, const void* __restrict__ xt,
         float* __restrict__ out, int vocab, int npos, unsigned long long total) {
    const int tid = threadIdx.x;
    const int t = blockIdx.x * BLK + tid;      // vector index
    const int base = 4 * t;                    // first element index

    // ---- 1) one LDG.128: data for 4 positions AND the dtype sample.
    unsigned wv[4] = {0u, 0u, 0u, 0u};
    const bool full = (base + 3 < npos);
    if (full) {
        uint4 v = ((const uint4*)xt)[t];
        wv[0] = v.x; wv[1] = v.y; wv[2] = v.z; wv[3] = v.w;
    } else {
        const unsigned* w = (const unsigned*)xt;
        for (int j = 0; j < 4; ++j)
            if (base + j < npos) wv[j] = w[base + j];
    }

    // per-warp dtype consensus (64 sampled odd words per warp):
    //  float32: any word >= 0x01000000 (tokens >= 1.0 -> >= 0x3F800000) -> mode 2
    //  int64:   odd words are hi-halves of small tokens -> all zero     -> mode 1
    //  int32:   odd words are random tokens -> some nonzero, none large -> mode 0
    bool p_large = full && ((wv[0] | wv[1] | wv[2] | wv[3]) >= 0x01000000u);
    bool p_nz    = full && ((wv[1] | wv[3]) != 0u);
    unsigned m_large = __ballot_sync(0xFFFFFFFFu, p_large);
    unsigned m_nz    = __ballot_sync(0xFFFFFFFFu, p_nz);
    const int mode = m_large ? 2 : (m_nz ? 0 : 1);

    // ---- 2) fast path: convert + write 4 tokens, flag masked ones
    long long xv[4];
    int my_masked = 0;
    if (mode == 0) {
        for (int j = 0; j < 4; ++j) xv[j] = (long long)(int)wv[j];
    } else if (mode == 2) {
        for (int j = 0; j < 4; ++j) xv[j] = __float2ll_rn(__uint_as_float(wv[j]));
    } else { // int64: the uint4 covered the wrong bytes; reload proper elements
        for (int j = 0; j < 4; ++j)
            xv[j] = (base + j < npos) ? ((const long long*)xt)[base + j] : 0;
    }
    float f4[4];
    for (int j = 0; j < 4; ++j) {
        f4[j] = (float)xv[j];
        if (base + j < npos && xv[j] == MASK_ID) my_masked |= (1 << j);
    }
    if (full) {
        ((float4*)out)[t] = make_float4(f4[0], f4[1], f4[2], f4[3]);
    } else {
        for (int j = 0; j < 4; ++j)
            if (base + j < npos) out[base + j] = f4[j];
    }

    // single block-wide consensus; common case exits here
    if (!__syncthreads_or(my_masked)) return;

    // ---- 3) heavy path (rare): exact top-k -> top-p -> gumbel argmax
    __shared__ int s_masked[4 * BLK];
    __shared__ int s_nmask;
    __shared__ int s_cnt;
    __shared__ float sval[TOPK];
    __shared__ int   sidx[TOPK];
    __shared__ int   s_ng, s_neq;
    __shared__ int   eq_idx[128];

    if (tid == 0) s_nmask = 0;
    __syncthreads();
    for (int j = 0; j < 4; ++j)
        if (my_masked & (1 << j)) {
            int p = atomicAdd(&s_nmask, 1);
            s_masked[p] = base + j;
        }
    __syncthreads();
    const int nmask = s_nmask;

    for (int mi = 0; mi < nmask; ++mi) {
        const int row_r = s_masked[mi];
        const float* row = logits + (size_t)row_r * (size_t)vocab;

        // 3a) 50th-largest key via MSB-first binary search
        unsigned T = 0;
        for (int bit = 31; bit >= 0; --bit) {
            unsigned cand = T | (1u << bit);
            if (tid == 0) s_cnt = 0;
            __syncthreads();
            int c = 0;
            for (int v = tid; v < vocab; v += BLK)
                c += (f2key(row[v]) >= cand);
            if (c) atomicAdd(&s_cnt, c);
            __syncthreads();
            int cnt = s_cnt;
            __syncthreads();
            if (cnt >= TOPK) T = cand;
        }

        // 3b) count strictly greater
        if (tid == 0) s_cnt = 0;
        __syncthreads();
        {
            int c = 0;
            for (int v = tid; v < vocab; v += BLK)
                c += (f2key(row[v]) > T);
            if (c) atomicAdd(&s_cnt, c);
        }
        __syncthreads();
        const int n_greater = s_cnt;            // <= 49
        const int need_eq = TOPK - n_greater;   // >= 1
        __syncthreads();

        // 3c) gather the top-k set (stable tie-break by lowest index)
        if (tid == 0) { s_ng = 0; s_neq = 0; }
        __syncthreads();
        for (int v = tid; v < vocab; v += BLK) {
            unsigned k = f2key(row[v]);
            if (k > T) {
                int p = atomicAdd(&s_ng, 1);
                sval[p] = row[v]; sidx[p] = v;
            } else if (k == T) {
                int p = atomicAdd(&s_neq, 1);
                if (p < 128) eq_idx[p] = v;
            }
        }
        __syncthreads();

        if (tid == 0) {
            int ne = s_neq; if (ne > 128) ne = 128;
            for (int a = 0; a < need_eq; ++a) {
                int mb = a;
                for (int b2 = a + 1; b2 < ne; ++b2)
                    if (eq_idx[b2] < eq_idx[mb]) mb = b2;
                int tt = eq_idx[a]; eq_idx[a] = eq_idx[mb]; eq_idx[mb] = tt;
                sval[n_greater + a] = row[eq_idx[a]];
                sidx[n_greater + a] = eq_idx[a];
            }
            // sort 50: descending value, tie -> ascending index
            for (int a = 1; a < TOPK; ++a) {
                float v = sval[a]; int ix = sidx[a];
                int b2 = a - 1;
                while (b2 >= 0 && (sval[b2] < v || (sval[b2] == v && sidx[b2] > ix))) {
                    sval[b2 + 1] = sval[b2]; sidx[b2 + 1] = sidx[b2]; --b2;
                }
                sval[b2 + 1] = v; sidx[b2 + 1] = ix;
            }
            // softmax + right-shifted cumsum nucleus cutoff (prefix of length m)
            float vmax = sval[0];
            float e[TOPK];
            float denom = 0.f;
            for (int j = 0; j < TOPK; ++j) { e[j] = expf(sval[j] - vmax); denom += e[j]; }
            float cumprev = 0.f;
            int m = 0;
            for (int j = 0; j < TOPK; ++j) {
                if (j != 0 && !(cumprev <= TOPP)) break;
                ++m;
                cumprev += e[j] / denom;
            }
            // gumbel-argmax over survivors; tie -> smallest vocab index
            unsigned long long half = total >> 1;
            float best = -1e30f; int besti = 0x7fffffff;
            for (int j = 0; j < m; ++j) {
                unsigned long long i =
                    (unsigned long long)row_r * (unsigned long long)vocab
                    + (unsigned long long)sidx[j];
                float score = sval[j] + gumbel_at(i, half);
                if (score > best || (score == best && sidx[j] < besti)) {
                    best = score; besti = sidx[j];
                }
            }
            out[row_r] = (float)besti;
        }
        __syncthreads();
    }
}

extern "C" void kernel_launch(void* const* d_in, const int* in_sizes, int n_in,
                              void* d_out, int out_size) {
    int li = 0, xi = 1;
    if (n_in >= 2 && in_sizes[1] > in_sizes[0]) { li = 1; xi = 0; }  // logits = bigger input
    const float* logits = (const float*)d_in[li];
    const void*  xt     = d_in[xi];
    const int npos  = out_size;                     // B*S = 2048
    const int vocab = in_sizes[li] / npos;          // 50257
    const unsigned long long total = (unsigned long long)in_sizes[li];

    int nvec = (npos + 3) / 4;
    rd_fused<<<(nvec + BLK - 1) / BLK, BLK>>>(logits, xt, (float*)d_out, vocab, npos, total);
}

// round 6
// speedup vs baseline: 2.3916x; 1.2238x over previous
#include <cuda_runtime.h>
#include <cstdint>

// ReverseDiffusion: out = where(x_t == 50256, categorical(key42, topk_topp(logits)), x_t)
// Common path is warp-autonomous (no block sync, no smem). Rare masked rows are
// sampled warp-cooperatively with exact JAX threefry/top-k/top-p semantics.

#define TOPK 50
#define TOPP 0.9f
#define MASK_ID 50256LL
#define BLK 128
#define NWARP (BLK / 32)
#define FULLM 0xFFFFFFFFu

// ---------------- helpers ----------------
__device__ __forceinline__ unsigned f2key(float f) {
    unsigned u = __float_as_uint(f);
    return (u & 0x80000000u) ? ~u : (u | 0x80000000u);
}
__device__ __forceinline__ unsigned rotl32(unsigned x, int n) {
    return (x << n) | (x >> (32 - n));
}

// JAX threefry2x32, key = (0, 42)
__device__ void threefry_0_42(unsigned x0, unsigned x1, unsigned& o0, unsigned& o1) {
    const unsigned k0 = 0u, k1 = 42u;
    const unsigned k2 = k0 ^ k1 ^ 0x1BD11BDAu;
    unsigned v0 = x0 + k0, v1 = x1 + k1;
#define TF_ROUND(r) { v0 += v1; v1 = rotl32(v1, r); v1 ^= v0; }
    TF_ROUND(13) TF_ROUND(15) TF_ROUND(26) TF_ROUND(6)
    v0 += k1; v1 += k2 + 1u;
    TF_ROUND(17) TF_ROUND(29) TF_ROUND(16) TF_ROUND(24)
    v0 += k2; v1 += k0 + 2u;
    TF_ROUND(13) TF_ROUND(15) TF_ROUND(26) TF_ROUND(6)
    v0 += k0; v1 += k1 + 3u;
    TF_ROUND(17) TF_ROUND(29) TF_ROUND(16) TF_ROUND(24)
    v0 += k1; v1 += k2 + 4u;
    TF_ROUND(13) TF_ROUND(15) TF_ROUND(26) TF_ROUND(6)
    v0 += k2; v1 += k0 + 5u;
#undef TF_ROUND
    o0 = v0; o1 = v1;
}

// gumbel noise at flat index i, exactly as jax.random.gumbel(key(42), shape)
__device__ float gumbel_at(unsigned long long i, unsigned long long half) {
    unsigned x0, x1, o0, o1;
    if (i < half) { x0 = (unsigned)i;          x1 = (unsigned)(i + half); }
    else          { x0 = (unsigned)(i - half); x1 = (unsigned)i;          }
    threefry_0_42(x0, x1, o0, o1);
    unsigned bits = (i < half) ? o0 : o1;
    float u = __uint_as_float((bits >> 9) | 0x3f800000u) - 1.0f;
    u = fmaxf(u, 1.17549435e-38f);
    return -logf(-logf(u));
}

__device__ __forceinline__ int warp_sum(int c) {
#if __CUDA_ARCH__ >= 800
    return __reduce_add_sync(FULLM, c);
#else
    for (int o = 16; o; o >>= 1) c += __shfl_xor_sync(FULLM, c, o);
    return c;
#endif
}

// ---------------- warp-cooperative exact sampler for one row ----------------
__device__ void sample_row_warp(const float* __restrict__ row, float* __restrict__ out,
                                int row_r, int vocab, unsigned long long total,
                                int lane, int wslot,
                                float (*sval)[TOPK], int (*sidx)[TOPK],
                                int* s_ng, int* s_neq, int (*eq_idx)[128]) {
    // 1) 50th-largest key via MSB-first binary search (warp-reduced counts)
    unsigned T = 0;
    for (int bit = 31; bit >= 0; --bit) {
        unsigned cand = T | (1u << bit);
        int c = 0;
        for (int v = lane; v < vocab; v += 32)
            c += (f2key(row[v]) >= cand);
        if (warp_sum(c) >= TOPK) T = cand;
    }

    // 2) count strictly greater
    int cg = 0;
    for (int v = lane; v < vocab; v += 32)
        cg += (f2key(row[v]) > T);
    const int n_greater = warp_sum(cg);     // <= 49
    const int need_eq = TOPK - n_greater;   // >= 1

    // 3) gather the top-k set (per-warp shared scratch)
    if (lane == 0) { s_ng[wslot] = 0; s_neq[wslot] = 0; }
    __syncwarp();
    for (int v = lane; v < vocab; v += 32) {
        unsigned k = f2key(row[v]);
        if (k > T) {
            int p = atomicAdd(&s_ng[wslot], 1);
            sval[wslot][p] = row[v]; sidx[wslot][p] = v;
        } else if (k == T) {
            int p = atomicAdd(&s_neq[wslot], 1);
            if (p < 128) eq_idx[wslot][p] = v;
        }
    }
    __syncwarp();

    if (lane == 0) {
        float* sv = sval[wslot];
        int*   si = sidx[wslot];
        int*   eq = eq_idx[wslot];
        int ne = s_neq[wslot]; if (ne > 128) ne = 128;
        // pick need_eq smallest indices among threshold-equal tokens
        for (int a = 0; a < need_eq; ++a) {
            int mb = a;
            for (int b2 = a + 1; b2 < ne; ++b2)
                if (eq[b2] < eq[mb]) mb = b2;
            int tt = eq[a]; eq[a] = eq[mb]; eq[mb] = tt;
            sv[n_greater + a] = row[eq[a]];
            si[n_greater + a] = eq[a];
        }
        // sort 50: descending value, tie -> ascending index
        for (int a = 1; a < TOPK; ++a) {
            float v = sv[a]; int ix = si[a];
            int b2 = a - 1;
            while (b2 >= 0 && (sv[b2] < v || (sv[b2] == v && si[b2] > ix))) {
                sv[b2 + 1] = sv[b2]; si[b2 + 1] = si[b2]; --b2;
            }
            sv[b2 + 1] = v; si[b2 + 1] = ix;
        }
        // softmax + right-shifted cumsum nucleus cutoff (prefix of length m)
        float vmax = sv[0];
        float e[TOPK];
        float denom = 0.f;
        for (int j = 0; j < TOPK; ++j) { e[j] = expf(sv[j] - vmax); denom += e[j]; }
        float cumprev = 0.f;
        int m = 0;
        for (int j = 0; j < TOPK; ++j) {
            if (j != 0 && !(cumprev <= TOPP)) break;
            ++m;
            cumprev += e[j] / denom;
        }
        // gumbel-argmax over survivors; tie -> smallest vocab index
        unsigned long long half = total >> 1;
        float best = -1e30f; int besti = 0x7fffffff;
        for (int j = 0; j < m; ++j) {
            unsigned long long i =
                (unsigned long long)row_r * (unsigned long long)vocab
                + (unsigned long long)si[j];
            float score = sv[j] + gumbel_at(i, half);
            if (score > best || (score == best && si[j] < besti)) {
                best = score; besti = si[j];
            }
        }
        out[row_r] = (float)besti;
    }
    __syncwarp();
}

// ---------------- single fused kernel ----------------
// Each thread owns 4 consecutive positions; warps are fully independent.
__global__ void __launch_bounds__(BLK)
rd_fused(const float* __restrict__ logits, const void* __restrict__ xt,
         float* __restrict__ out, int vocab, int npos, unsigned long long total) {
    const int tid  = threadIdx.x;
    const int lane = tid & 31;
    const int wid  = tid >> 5;
    const int t    = blockIdx.x * BLK + tid;   // vector index
    const int base = 4 * t;

    // ---- 1) one LDG.128: data for 4 positions AND the dtype sample
    unsigned wv[4] = {0u, 0u, 0u, 0u};
    const bool full = (base + 3 < npos);
    if (full) {
        uint4 v = ((const uint4*)xt)[t];
        wv[0] = v.x; wv[1] = v.y; wv[2] = v.z; wv[3] = v.w;
    } else {
        const unsigned* w = (const unsigned*)xt;
        for (int j = 0; j < 4; ++j)
            if (base + j < npos) wv[j] = w[base + j];
    }

    // per-warp dtype consensus (128 sampled words / 64 odd words per warp):
    //  float32: any word >= 0x01000000 (tokens >= 1.0)             -> mode 2
    //  int64:   odd words are hi-halves of small tokens, all zero  -> mode 1
    //  int32:   odd words random tokens -> some nonzero, none large-> mode 0
    bool p_large = full && ((wv[0] | wv[1] | wv[2] | wv[3]) >= 0x01000000u);
    bool p_nz    = full && ((wv[1] | wv[3]) != 0u);
    unsigned m_large = __ballot_sync(FULLM, p_large);
    unsigned m_nz    = __ballot_sync(FULLM, p_nz);
    const int mode = m_large ? 2 : (m_nz ? 0 : 1);

    // ---- 2) fast path: convert + write 4 tokens, flag masked ones
    long long xv[4];
    if (mode == 0) {
        for (int j = 0; j < 4; ++j) xv[j] = (long long)(int)wv[j];
    } else if (mode == 2) {
        for (int j = 0; j < 4; ++j) xv[j] = __float2ll_rn(__uint_as_float(wv[j]));
    } else { // int64: reload proper 8-byte elements
        for (int j = 0; j < 4; ++j)
            xv[j] = (base + j < npos) ? ((const long long*)xt)[base + j] : 0;
    }
    int my_masked = 0;
    float f4[4];
    for (int j = 0; j < 4; ++j) {
        f4[j] = (float)xv[j];
        if (base + j < npos && xv[j] == MASK_ID) my_masked |= (1 << j);
    }
    if (full) {
        ((float4*)out)[t] = make_float4(f4[0], f4[1], f4[2], f4[3]);
    } else {
        for (int j = 0; j < 4; ++j)
            if (base + j < npos) out[base + j] = f4[j];
    }

    // warp-local consensus; common case: warp retires immediately, no block sync
    unsigned act = __ballot_sync(FULLM, my_masked != 0);
    if (!act) return;

    // ---- 3) heavy path (rare): warp-cooperative exact sampling
    __shared__ float sval[NWARP][TOPK];
    __shared__ int   sidx[NWARP][TOPK];
    __shared__ int   s_ng[NWARP], s_neq[NWARP];
    __shared__ int   eq_idx[NWARP][128];

    while (act) {
        int l = __ffs(act) - 1; act &= act - 1;
        int mm    = __shfl_sync(FULLM, my_masked, l);
        int lbase = 4 * (blockIdx.x * BLK + wid * 32 + l);
        for (int j = 0; j < 4; ++j) {
            if ((mm >> j) & 1) {
                int row_r = lbase + j;
                sample_row_warp(logits + (size_t)row_r * (size_t)vocab, out,
                                row_r, vocab, total, lane, wid,
                                sval, sidx, s_ng, s_neq, eq_idx);
            }
        }
    }
}

extern "C" void kernel_launch(void* const* d_in, const int* in_sizes, int n_in,
                              void* d_out, int out_size) {
    int li = 0, xi = 1;
    if (n_in >= 2 && in_sizes[1] > in_sizes[0]) { li = 1; xi = 0; }  // logits = bigger input
    const float* logits = (const float*)d_in[li];
    const void*  xt     = d_in[xi];
    const int npos  = out_size;                     // B*S = 2048
    const int vocab = in_sizes[li] / npos;          // 50257
    const unsigned long long total = (unsigned long long)in_sizes[li];

    int nvec = (npos + 3) / 4;
    rd_fused<<<(nvec + BLK - 1) / BLK, BLK>>>(logits, xt, (float*)d_out, vocab, npos, total);
}